// round 6
// baseline (speedup 1.0000x reference)
#include <cuda_runtime.h>

#define SLEN 4096
#define DM   1024
#define NH   16
#define DH   64
#define QKV_LD (3*DM)

// Scratch (device globals; no allocation allowed in kernel_launch)
__device__ float g_qkv[(size_t)SLEN * QKV_LD];   // [S, 3D]
__device__ float g_attn[(size_t)SLEN * DM];      // [S, D]

// ---------------------------------------------------------------------------
// SGEMM with bias: C[M,N] = A[M,K] @ B[K,N] + bias[N]
// M%128==0, N%128==0, K%16==0 (all shapes here satisfy this)
// 128x128 block tile, 16 K-tile, 8x8 per thread, 256 threads.
// Block index swizzled for L2 reuse of the B (weight) tiles.
// ---------------------------------------------------------------------------
__global__ __launch_bounds__(256, 2)
void sgemm_bias_kernel(const float* __restrict__ A, const float* __restrict__ B,
                       const float* __restrict__ bias, float* __restrict__ C,
                       int M, int N, int K)
{
    const int BM = 128, BN = 128, BK = 16;
    __shared__ float As[BK][BM + 4];   // A transposed: As[k][m]
    __shared__ float Bs[BK][BN];       // Bs[k][n]

    int tid = threadIdx.x;
    int tx = tid & 15;        // 0..15 -> output col group
    int ty = tid >> 4;        // 0..15 -> output row group

    // L2 swizzle: walk M in groups of 8 row-tiles per N-stripe so consecutive
    // CTAs share the same B tile (weights stay hot in L2).
    int nbm = M / BM, nbn = N / BN;
    int lin = (int)blockIdx.y * gridDim.x + (int)blockIdx.x;
    const int GRP = 8;
    int tiles_per_stripe = GRP * nbn;
    int stripe = lin / tiles_per_stripe;
    int rem    = lin % tiles_per_stripe;
    int rows_here = min(GRP, nbm - stripe * GRP);
    int bn = rem / rows_here;
    int bm = stripe * GRP + rem % rows_here;

    const float* Ag = A + (size_t)bm * BM * K;
    const float* Bg = B + (size_t)bn * BN;

    int arow = tid >> 2;          // 0..63
    int acol = (tid & 3) << 2;    // 0,4,8,12
    int brow = tid >> 5;          // 0..7
    int bcol = (tid & 31) << 2;   // 0..124

    float acc[8][8];
#pragma unroll
    for (int i = 0; i < 8; i++)
#pragma unroll
        for (int j = 0; j < 8; j++) acc[i][j] = 0.f;

    int nk = K / BK;
    for (int kt = 0; kt < nk; kt++) {
        float4 a0 = *(const float4*)(Ag + (size_t)arow        * K + kt * BK + acol);
        float4 a1 = *(const float4*)(Ag + (size_t)(arow + 64) * K + kt * BK + acol);
        float4 b0 = *(const float4*)(Bg + (size_t)(kt * BK + brow)     * N + bcol);
        float4 b1 = *(const float4*)(Bg + (size_t)(kt * BK + brow + 8) * N + bcol);
        __syncthreads();
        As[acol + 0][arow] = a0.x; As[acol + 1][arow] = a0.y;
        As[acol + 2][arow] = a0.z; As[acol + 3][arow] = a0.w;
        As[acol + 0][arow + 64] = a1.x; As[acol + 1][arow + 64] = a1.y;
        As[acol + 2][arow + 64] = a1.z; As[acol + 3][arow + 64] = a1.w;
        *(float4*)&Bs[brow][bcol]     = b0;
        *(float4*)&Bs[brow + 8][bcol] = b1;
        __syncthreads();

#pragma unroll
        for (int k = 0; k < BK; k++) {
            float4 av0 = *(const float4*)&As[k][ty * 8];
            float4 av1 = *(const float4*)&As[k][ty * 8 + 4];
            float4 bv0 = *(const float4*)&Bs[k][tx * 8];
            float4 bv1 = *(const float4*)&Bs[k][tx * 8 + 4];
            float a8[8] = {av0.x, av0.y, av0.z, av0.w, av1.x, av1.y, av1.z, av1.w};
            float b8[8] = {bv0.x, bv0.y, bv0.z, bv0.w, bv1.x, bv1.y, bv1.z, bv1.w};
#pragma unroll
            for (int i = 0; i < 8; i++)
#pragma unroll
                for (int j = 0; j < 8; j++)
                    acc[i][j] += a8[i] * b8[j];
        }
    }

#pragma unroll
    for (int i = 0; i < 8; i++) {
        size_t row = (size_t)bm * BM + ty * 8 + i;
        float* Cr = C + row * N + (size_t)bn * BN + tx * 8;
        const float* br = bias + (size_t)bn * BN + tx * 8;
        float4 o0 = make_float4(acc[i][0] + br[0], acc[i][1] + br[1],
                                acc[i][2] + br[2], acc[i][3] + br[3]);
        float4 o1 = make_float4(acc[i][4] + br[4], acc[i][5] + br[5],
                                acc[i][6] + br[6], acc[i][7] + br[7]);
        *(float4*)(Cr)     = o0;
        *(float4*)(Cr + 4) = o1;
    }
}

// ---------------------------------------------------------------------------
// Fused causal attention (flash style), fp32.
// One block = one (query-block of 64, head). 256 threads (16x16), each owns a
// 4x4 tile of the 64x64 score block and a 4x4 tile of the 64x64 output.
// Online softmax with running max/sum. Mask input ignored (exactly causal).
// ---------------------------------------------------------------------------
__global__ __launch_bounds__(256, 2)
void attn_kernel(const float* __restrict__ qkv, float* __restrict__ out)
{
    extern __shared__ float sm[];
    const int P = 68;                 // smem pitch (floats), 16B-aligned rows
    float* Qt  = sm;                  // [DH][P]  Qt[d][i]  (Q^T, pre-scaled)
    float* KtP = sm + DH * P;         // [DH][P]  Kt[d][j]  -> reused as Ps[i][j]
    float* Vs  = sm + 2 * DH * P;     // [64][P]  Vs[j][d]

    int tid = threadIdx.x;
    int tx = tid & 15;                // key/dh col group
    int ty = tid >> 4;                // query row group
    int qb = 63 - (int)blockIdx.x;    // heavy (late) query blocks first
    int h  = blockIdx.y;

    const float* qbase = qkv + (size_t)h * DH;
    const float* kbase = qkv + DM     + (size_t)h * DH;
    const float* vbase = qkv + 2 * DM + (size_t)h * DH;

    // Load Q block transposed, pre-scaled by 1/sqrt(DH)=0.125
    {
        int r = tid >> 4;
        int c = (tid & 15) << 2;
#pragma unroll
        for (int p = 0; p < 4; p++) {
            int row = r + p * 16;
            float4 v = *(const float4*)(qbase + (size_t)(qb * 64 + row) * QKV_LD + c);
            Qt[(c + 0) * P + row] = v.x * 0.125f;
            Qt[(c + 1) * P + row] = v.y * 0.125f;
            Qt[(c + 2) * P + row] = v.z * 0.125f;
            Qt[(c + 3) * P + row] = v.w * 0.125f;
        }
    }

    float acc[4][4];
    float mrow[4], lrow[4];
#pragma unroll
    for (int i = 0; i < 4; i++) {
        mrow[i] = -1e30f; lrow[i] = 0.f;
#pragma unroll
        for (int j = 0; j < 4; j++) acc[i][j] = 0.f;
    }

    for (int kb = 0; kb <= qb; kb++) {
        __syncthreads();   // previous iteration's PV reads done; Q stores visible
        {
            int r = tid >> 4;
            int c = (tid & 15) << 2;
#pragma unroll
            for (int p = 0; p < 4; p++) {
                int row = r + p * 16;
                float4 kv = *(const float4*)(kbase + (size_t)(kb * 64 + row) * QKV_LD + c);
                KtP[(c + 0) * P + row] = kv.x;
                KtP[(c + 1) * P + row] = kv.y;
                KtP[(c + 2) * P + row] = kv.z;
                KtP[(c + 3) * P + row] = kv.w;
                float4 vv = *(const float4*)(vbase + (size_t)(kb * 64 + row) * QKV_LD + c);
                *(float4*)&Vs[row * P + c] = vv;
            }
        }
        __syncthreads();

        // S = (Q/8) @ K^T  (64x64x64)
        float s[4][4];
#pragma unroll
        for (int i = 0; i < 4; i++)
#pragma unroll
            for (int j = 0; j < 4; j++) s[i][j] = 0.f;

#pragma unroll 16
        for (int d = 0; d < DH; d++) {
            float4 qv = *(const float4*)&Qt[d * P + ty * 4];
            float4 kv = *(const float4*)&KtP[d * P + tx * 4];
            float qa[4] = {qv.x, qv.y, qv.z, qv.w};
            float ka[4] = {kv.x, kv.y, kv.z, kv.w};
#pragma unroll
            for (int i = 0; i < 4; i++)
#pragma unroll
                for (int j = 0; j < 4; j++)
                    s[i][j] += qa[i] * ka[j];
        }

        if (kb == qb) {   // diagonal block: mask strictly-future keys
#pragma unroll
            for (int i = 0; i < 4; i++)
#pragma unroll
                for (int j = 0; j < 4; j++)
                    if (tx * 4 + j > ty * 4 + i) s[i][j] = -1e30f;
        }

        // Online softmax bookkeeping; rows live on 16 consecutive lanes
#pragma unroll
        for (int i = 0; i < 4; i++) {
            float mx = fmaxf(fmaxf(s[i][0], s[i][1]), fmaxf(s[i][2], s[i][3]));
#pragma unroll
            for (int off = 8; off > 0; off >>= 1)
                mx = fmaxf(mx, __shfl_xor_sync(0xffffffffu, mx, off));
            float mnew = fmaxf(mrow[i], mx);
            float corr = __expf(mrow[i] - mnew);
            float rs = 0.f;
#pragma unroll
            for (int j = 0; j < 4; j++) {
                float e = __expf(s[i][j] - mnew);
                s[i][j] = e;
                rs += e;
            }
#pragma unroll
            for (int off = 8; off > 0; off >>= 1)
                rs += __shfl_xor_sync(0xffffffffu, rs, off);
            lrow[i] = lrow[i] * corr + rs;
            mrow[i] = mnew;
#pragma unroll
            for (int j = 0; j < 4; j++) acc[i][j] *= corr;
        }

        __syncthreads();   // Kt reads complete; safe to overwrite as Ps
#pragma unroll
        for (int i = 0; i < 4; i++)
            *(float4*)&KtP[(ty * 4 + i) * P + tx * 4] =
                make_float4(s[i][0], s[i][1], s[i][2], s[i][3]);
        __syncthreads();

        // acc += P @ V  (64x64x64)
#pragma unroll 8
        for (int j = 0; j < 64; j++) {
            float pr0 = KtP[(ty * 4 + 0) * P + j];
            float pr1 = KtP[(ty * 4 + 1) * P + j];
            float pr2 = KtP[(ty * 4 + 2) * P + j];
            float pr3 = KtP[(ty * 4 + 3) * P + j];
            float4 vv = *(const float4*)&Vs[j * P + tx * 4];
            acc[0][0] += pr0 * vv.x; acc[0][1] += pr0 * vv.y;
            acc[0][2] += pr0 * vv.z; acc[0][3] += pr0 * vv.w;
            acc[1][0] += pr1 * vv.x; acc[1][1] += pr1 * vv.y;
            acc[1][2] += pr1 * vv.z; acc[1][3] += pr1 * vv.w;
            acc[2][0] += pr2 * vv.x; acc[2][1] += pr2 * vv.y;
            acc[2][2] += pr2 * vv.z; acc[2][3] += pr2 * vv.w;
            acc[3][0] += pr3 * vv.x; acc[3][1] += pr3 * vv.y;
            acc[3][2] += pr3 * vv.z; acc[3][3] += pr3 * vv.w;
        }
    }

    // Normalize and write merged-head layout [S, D]
#pragma unroll
    for (int i = 0; i < 4; i++) {
        float inv = 1.f / lrow[i];
        size_t row = (size_t)qb * 64 + ty * 4 + i;
        float4 o = make_float4(acc[i][0] * inv, acc[i][1] * inv,
                               acc[i][2] * inv, acc[i][3] * inv);
        *(float4*)(out + row * DM + (size_t)h * DH + tx * 4) = o;
    }
}

// ---------------------------------------------------------------------------
extern "C" void kernel_launch(void* const* d_in, const int* in_sizes, int n_in,
                              void* d_out, int out_size)
{
    const float* x      = (const float*)d_in[0];
    // d_in[1] = additive causal mask — exactly causal, handled analytically
    const float* W_attn = (const float*)d_in[2];
    const float* b_attn = (const float*)d_in[3];
    const float* W_proj = (const float*)d_in[4];
    const float* b_proj = (const float*)d_in[5];
    float* out = (float*)d_out;

    float *qkv_ptr, *attn_ptr;
    cudaGetSymbolAddress((void**)&qkv_ptr, g_qkv);
    cudaGetSymbolAddress((void**)&attn_ptr, g_attn);

    // 1) QKV projection: [4096,1024] @ [1024,3072]
    sgemm_bias_kernel<<<dim3(3 * DM / 128, SLEN / 128), 256>>>(
        x, W_attn, b_attn, qkv_ptr, SLEN, 3 * DM, DM);

    // 2) Fused causal attention
    size_t smem = (size_t)3 * DH * 68 * sizeof(float);   // 52224 B
    cudaFuncSetAttribute(attn_kernel,
                         cudaFuncAttributeMaxDynamicSharedMemorySize, (int)smem);
    attn_kernel<<<dim3(SLEN / 64, NH), 256, smem>>>(qkv_ptr, attn_ptr);

    // 3) Output projection: [4096,1024] @ [1024,1024]
    sgemm_bias_kernel<<<dim3(DM / 128, SLEN / 128), 256>>>(
        attn_ptr, W_proj, b_proj, out, SLEN, DM, DM);
}

// round 8
// speedup vs baseline: 1.3446x; 1.3446x over previous
#include <cuda_runtime.h>
#include <cuda_bf16.h>
#include <cstdint>

#define SLEN 4096
#define DM   1024
#define NH   16
#define DH   64
#define QKV_LD (3*DM)

// ---------------- device-global scratch (no allocs allowed) ----------------
__device__ float g_qkv[(size_t)SLEN * QKV_LD];     // [S, 3D] fp32
__device__ float g_attn[(size_t)SLEN * DM];        // [S, D]  fp32
__device__ __nv_bfloat16 g_xh[(size_t)SLEN * DM], g_xl[(size_t)SLEN * DM];   // x split [S,K]
__device__ __nv_bfloat16 g_wah[(size_t)3*DM*DM],  g_wal[(size_t)3*DM*DM];    // W_attn^T split [N,K]
__device__ __nv_bfloat16 g_wph[(size_t)DM*DM],    g_wpl[(size_t)DM*DM];      // W_proj^T split [N,K]
__device__ __nv_bfloat16 g_ah[(size_t)SLEN * DM], g_al[(size_t)SLEN * DM];   // attn out split [S,K]

// ---------------- helpers ----------------
__device__ __forceinline__ uint32_t smem_u32(const void* p) {
    uint32_t a;
    asm("{ .reg .u64 t; cvta.to.shared.u64 t, %1; cvt.u32.u64 %0, t; }" : "=r"(a) : "l"(p));
    return a;
}
__device__ __forceinline__ void cp16(uint32_t s, const void* g) {
    asm volatile("cp.async.cg.shared.global [%0], [%1], 16;" :: "r"(s), "l"(g));
}
__device__ __forceinline__ void ldsm4(uint32_t a, uint32_t r[4]) {
    asm volatile("ldmatrix.sync.aligned.m8n8.x4.shared.b16 {%0,%1,%2,%3}, [%4];"
                 : "=r"(r[0]), "=r"(r[1]), "=r"(r[2]), "=r"(r[3]) : "r"(a));
}
__device__ __forceinline__ void mma16816(float c[4], const uint32_t a[4], uint32_t b0, uint32_t b1) {
    asm volatile("mma.sync.aligned.m16n8k16.row.col.f32.bf16.bf16.f32 "
                 "{%0,%1,%2,%3}, {%4,%5,%6,%7}, {%8,%9}, {%0,%1,%2,%3};"
                 : "+f"(c[0]), "+f"(c[1]), "+f"(c[2]), "+f"(c[3])
                 : "r"(a[0]), "r"(a[1]), "r"(a[2]), "r"(a[3]), "r"(b0), "r"(b1));
}

// ---------------- pre-pass: fp32 -> bf16 hi/lo split ----------------
__device__ __forceinline__ uint32_t pk2(__nv_bfloat16 a, __nv_bfloat16 b) {
    __nv_bfloat162 t(a, b);
    return *(uint32_t*)&t;
}
__global__ void split_kernel(const float4* __restrict__ in, uint2* __restrict__ hi,
                             uint2* __restrict__ lo, int n4)
{
    int i = blockIdx.x * 256 + threadIdx.x;
    if (i >= n4) return;
    float4 v = in[i];
    __nv_bfloat16 h0 = __float2bfloat16(v.x), h1 = __float2bfloat16(v.y);
    __nv_bfloat16 h2 = __float2bfloat16(v.z), h3 = __float2bfloat16(v.w);
    __nv_bfloat16 l0 = __float2bfloat16(v.x - __bfloat162float(h0));
    __nv_bfloat16 l1 = __float2bfloat16(v.y - __bfloat162float(h1));
    __nv_bfloat16 l2 = __float2bfloat16(v.z - __bfloat162float(h2));
    __nv_bfloat16 l3 = __float2bfloat16(v.w - __bfloat162float(h3));
    hi[i] = make_uint2(pk2(h0, h1), pk2(h2, h3));
    lo[i] = make_uint2(pk2(l0, l1), pk2(l2, l3));
}

// ---------------- pre-pass: transpose + split  W[K,N] -> T[N,K] hi/lo ----------------
__global__ void tsplit_kernel(const float* __restrict__ W, __nv_bfloat16* __restrict__ Th,
                              __nv_bfloat16* __restrict__ Tl, int K, int N)
{
    __shared__ float t[32][33];
    int bx = blockIdx.x, by = blockIdx.y;   // bx: N/32, by: K/32
    int x = bx * 32 + threadIdx.x;
#pragma unroll
    for (int i = 0; i < 32; i += 8)
        t[threadIdx.y + i][threadIdx.x] = W[(size_t)(by * 32 + threadIdx.y + i) * N + x];
    __syncthreads();
    int kx = by * 32 + threadIdx.x;
#pragma unroll
    for (int i = 0; i < 32; i += 8) {
        float v = t[threadIdx.x][threadIdx.y + i];
        __nv_bfloat16 h = __float2bfloat16(v);
        size_t o = (size_t)(bx * 32 + threadIdx.y + i) * K + kx;
        Th[o] = h;
        Tl[o] = __float2bfloat16(v - __bfloat162float(h));
    }
}

// ---------------------------------------------------------------------------
// mma.sync GEMM:  C[M,N] = (Ah+Al)[M,K] @ (Bh+Bl)[N,K]^T + bias
// bf16 split-precision (3 HMMA terms), 128x128 CTA tile, 8 warps (4x2),
// warp tile 32x64, K-chunks of 64, 2-stage cp.async pipeline, XOR-8 swizzle.
// ---------------------------------------------------------------------------
#define KC        64
#define TILE_B    16384                 // 128 rows * 128 bytes (one operand tile)
#define STG_B     (4 * TILE_B)          // Ah, Al, Bh, Bl
#define GEMM_SMEM (2 * STG_B)           // 131072 B

__global__ __launch_bounds__(256, 1)
void mma_gemm(const __nv_bfloat16* __restrict__ Ah, const __nv_bfloat16* __restrict__ Al,
              const __nv_bfloat16* __restrict__ Bh, const __nv_bfloat16* __restrict__ Bl,
              const float* __restrict__ bias, float* __restrict__ C,
              int M, int N, int K)
{
    extern __shared__ char smem[];
    uint32_t sb = smem_u32(smem);
    int tid = threadIdx.x;
    int l   = tid & 31;
    int wid = tid >> 5;
    int bn = blockIdx.x, bm = blockIdx.y;

    // ---- loader mapping: 32 row-groups x 8 sixteen-byte cols ----
    int rb  = tid >> 3;                               // 0..31
    int c16 = tid & 7;                                // 16B col
    uint32_t sw = (uint32_t)((c16 ^ (rb & 7)) << 4);  // row-invariant (rows step by 32)

    const __nv_bfloat16* A0h = Ah + (size_t)(bm * 128 + rb) * K + c16 * 8;
    const __nv_bfloat16* A0l = Al + (size_t)(bm * 128 + rb) * K + c16 * 8;
    const __nv_bfloat16* B0h = Bh + (size_t)(bn * 128 + rb) * K + c16 * 8;
    const __nv_bfloat16* B0l = Bl + (size_t)(bn * 128 + rb) * K + c16 * 8;

    auto load_chunk = [&](int c, int st) {
        uint32_t s0 = sb + st * STG_B;
        size_t gofs = (size_t)c * KC;
#pragma unroll
        for (int p = 0; p < 4; p++) {
            uint32_t so = (uint32_t)(rb + 32 * p) * 128 + sw;
            size_t go = (size_t)(32 * p) * K + gofs;
            cp16(s0 + so,              A0h + go);
            cp16(s0 + TILE_B + so,     A0l + go);
            cp16(s0 + 2 * TILE_B + so, B0h + go);
            cp16(s0 + 3 * TILE_B + so, B0l + go);
        }
        asm volatile("cp.async.commit_group;" ::: "memory");
    };

    // ---- compute mapping ----
    int wm = wid >> 1;            // 0..3 -> m block of 32
    int wn = wid & 1;             // 0..1 -> n block of 64
    int m0 = wm * 32;
    int n0 = wn * 64;

    int rowA_lane = l & 15;             // A ldmatrix lane row
    int k16A      = l >> 4;             // A lane k16 offset (0/1)
    int r7a       = rowA_lane & 7;
    int rowB_lane = (l & 7) + 8 * (l >> 4);   // B ldmatrix lane row (n)
    int k16B      = (l >> 3) & 1;             // B lane k16 offset
    int r7b       = l & 7;

    float acc[2][8][4];
#pragma unroll
    for (int mf = 0; mf < 2; mf++)
#pragma unroll
        for (int nf = 0; nf < 8; nf++)
#pragma unroll
            for (int q = 0; q < 4; q++) acc[mf][nf][q] = 0.f;

    auto compute = [&](int st) {
        uint32_t base = sb + st * STG_B;
#pragma unroll
        for (int ks = 0; ks < 4; ks++) {
            uint32_t ah[2][4], al[2][4];
#pragma unroll
            for (int mf = 0; mf < 2; mf++) {
                uint32_t row = (uint32_t)(m0 + mf * 16 + rowA_lane);
                uint32_t off = row * 128 + (uint32_t)(((ks * 2 + k16A) ^ r7a) << 4);
                ldsm4(base + off,          ah[mf]);
                ldsm4(base + TILE_B + off, al[mf]);
            }
#pragma unroll
            for (int nfp = 0; nfp < 4; nfp++) {
                uint32_t row = (uint32_t)(n0 + nfp * 16 + rowB_lane);
                uint32_t off = row * 128 + (uint32_t)(((ks * 2 + k16B) ^ r7b) << 4);
                uint32_t bh[4], bl[4];
                ldsm4(base + 2 * TILE_B + off, bh);
                ldsm4(base + 3 * TILE_B + off, bl);
#pragma unroll
                for (int mf = 0; mf < 2; mf++) {
#pragma unroll
                    for (int nf = 0; nf < 2; nf++) {
                        float* c = acc[mf][nfp * 2 + nf];
                        mma16816(c, ah[mf], bh[2 * nf], bh[2 * nf + 1]);   // Ah*Bh
                        mma16816(c, ah[mf], bl[2 * nf], bl[2 * nf + 1]);   // Ah*Bl
                        mma16816(c, al[mf], bh[2 * nf], bh[2 * nf + 1]);   // Al*Bh
                    }
                }
            }
        }
    };

    int NCH = K / KC;                 // 16
    load_chunk(0, 0);
    for (int j = 0; j < NCH; j++) {
        if (j + 1 < NCH) {
            load_chunk(j + 1, (j + 1) & 1);
            asm volatile("cp.async.wait_group 1;" ::: "memory");
        } else {
            asm volatile("cp.async.wait_group 0;" ::: "memory");
        }
        __syncthreads();
        compute(j & 1);
        __syncthreads();
    }

    // ---- epilogue: direct register stores + bias ----
#pragma unroll
    for (int mf = 0; mf < 2; mf++) {
        int r0 = bm * 128 + m0 + mf * 16 + (l >> 2);
#pragma unroll
        for (int nfp = 0; nfp < 4; nfp++) {
#pragma unroll
            for (int nf = 0; nf < 2; nf++) {
                int col = bn * 128 + n0 + nfp * 16 + nf * 8 + 2 * (l & 3);
                float2 bv = *(const float2*)&bias[col];
                const float* c = acc[mf][nfp * 2 + nf];
                *(float2*)&C[(size_t)r0 * N + col] =
                    make_float2(c[0] + bv.x, c[1] + bv.y);
                *(float2*)&C[(size_t)(r0 + 8) * N + col] =
                    make_float2(c[2] + bv.x, c[3] + bv.y);
            }
        }
    }
}

// ---------------------------------------------------------------------------
// Fused causal attention (flash style), fp32 — unchanged (verified R6).
// ---------------------------------------------------------------------------
__global__ __launch_bounds__(256, 2)
void attn_kernel(const float* __restrict__ qkv, float* __restrict__ out)
{
    extern __shared__ float sm[];
    const int P = 68;
    float* Qt  = sm;
    float* KtP = sm + DH * P;
    float* Vs  = sm + 2 * DH * P;

    int tid = threadIdx.x;
    int tx = tid & 15;
    int ty = tid >> 4;
    int qb = 63 - (int)blockIdx.x;
    int h  = blockIdx.y;

    const float* qbase = qkv + (size_t)h * DH;
    const float* kbase = qkv + DM     + (size_t)h * DH;
    const float* vbase = qkv + 2 * DM + (size_t)h * DH;

    {
        int r = tid >> 4;
        int c = (tid & 15) << 2;
#pragma unroll
        for (int p = 0; p < 4; p++) {
            int row = r + p * 16;
            float4 v = *(const float4*)(qbase + (size_t)(qb * 64 + row) * QKV_LD + c);
            Qt[(c + 0) * P + row] = v.x * 0.125f;
            Qt[(c + 1) * P + row] = v.y * 0.125f;
            Qt[(c + 2) * P + row] = v.z * 0.125f;
            Qt[(c + 3) * P + row] = v.w * 0.125f;
        }
    }

    float acc[4][4];
    float mrow[4], lrow[4];
#pragma unroll
    for (int i = 0; i < 4; i++) {
        mrow[i] = -1e30f; lrow[i] = 0.f;
#pragma unroll
        for (int j = 0; j < 4; j++) acc[i][j] = 0.f;
    }

    for (int kb = 0; kb <= qb; kb++) {
        __syncthreads();
        {
            int r = tid >> 4;
            int c = (tid & 15) << 2;
#pragma unroll
            for (int p = 0; p < 4; p++) {
                int row = r + p * 16;
                float4 kv = *(const float4*)(kbase + (size_t)(kb * 64 + row) * QKV_LD + c);
                KtP[(c + 0) * P + row] = kv.x;
                KtP[(c + 1) * P + row] = kv.y;
                KtP[(c + 2) * P + row] = kv.z;
                KtP[(c + 3) * P + row] = kv.w;
                float4 vv = *(const float4*)(vbase + (size_t)(kb * 64 + row) * QKV_LD + c);
                *(float4*)&Vs[row * P + c] = vv;
            }
        }
        __syncthreads();

        float s[4][4];
#pragma unroll
        for (int i = 0; i < 4; i++)
#pragma unroll
            for (int j = 0; j < 4; j++) s[i][j] = 0.f;

#pragma unroll 16
        for (int d = 0; d < DH; d++) {
            float4 qv = *(const float4*)&Qt[d * P + ty * 4];
            float4 kv = *(const float4*)&KtP[d * P + tx * 4];
            float qa[4] = {qv.x, qv.y, qv.z, qv.w};
            float ka[4] = {kv.x, kv.y, kv.z, kv.w};
#pragma unroll
            for (int i = 0; i < 4; i++)
#pragma unroll
                for (int j = 0; j < 4; j++)
                    s[i][j] += qa[i] * ka[j];
        }

        if (kb == qb) {
#pragma unroll
            for (int i = 0; i < 4; i++)
#pragma unroll
                for (int j = 0; j < 4; j++)
                    if (tx * 4 + j > ty * 4 + i) s[i][j] = -1e30f;
        }

#pragma unroll
        for (int i = 0; i < 4; i++) {
            float mx = fmaxf(fmaxf(s[i][0], s[i][1]), fmaxf(s[i][2], s[i][3]));
#pragma unroll
            for (int off = 8; off > 0; off >>= 1)
                mx = fmaxf(mx, __shfl_xor_sync(0xffffffffu, mx, off));
            float mnew = fmaxf(mrow[i], mx);
            float corr = __expf(mrow[i] - mnew);
            float rs = 0.f;
#pragma unroll
            for (int j = 0; j < 4; j++) {
                float e = __expf(s[i][j] - mnew);
                s[i][j] = e;
                rs += e;
            }
#pragma unroll
            for (int off = 8; off > 0; off >>= 1)
                rs += __shfl_xor_sync(0xffffffffu, rs, off);
            lrow[i] = lrow[i] * corr + rs;
            mrow[i] = mnew;
#pragma unroll
            for (int j = 0; j < 4; j++) acc[i][j] *= corr;
        }

        __syncthreads();
#pragma unroll
        for (int i = 0; i < 4; i++)
            *(float4*)&KtP[(ty * 4 + i) * P + tx * 4] =
                make_float4(s[i][0], s[i][1], s[i][2], s[i][3]);
        __syncthreads();

#pragma unroll 8
        for (int j = 0; j < 64; j++) {
            float pr0 = KtP[(ty * 4 + 0) * P + j];
            float pr1 = KtP[(ty * 4 + 1) * P + j];
            float pr2 = KtP[(ty * 4 + 2) * P + j];
            float pr3 = KtP[(ty * 4 + 3) * P + j];
            float4 vv = *(const float4*)&Vs[j * P + tx * 4];
            acc[0][0] += pr0 * vv.x; acc[0][1] += pr0 * vv.y;
            acc[0][2] += pr0 * vv.z; acc[0][3] += pr0 * vv.w;
            acc[1][0] += pr1 * vv.x; acc[1][1] += pr1 * vv.y;
            acc[1][2] += pr1 * vv.z; acc[1][3] += pr1 * vv.w;
            acc[2][0] += pr2 * vv.x; acc[2][1] += pr2 * vv.y;
            acc[2][2] += pr2 * vv.z; acc[2][3] += pr2 * vv.w;
            acc[3][0] += pr3 * vv.x; acc[3][1] += pr3 * vv.y;
            acc[3][2] += pr3 * vv.z; acc[3][3] += pr3 * vv.w;
        }
    }

#pragma unroll
    for (int i = 0; i < 4; i++) {
        float inv = 1.f / lrow[i];
        size_t row = (size_t)qb * 64 + ty * 4 + i;
        float4 o = make_float4(acc[i][0] * inv, acc[i][1] * inv,
                               acc[i][2] * inv, acc[i][3] * inv);
        *(float4*)(out + row * DM + (size_t)h * DH + tx * 4) = o;
    }
}

// ---------------------------------------------------------------------------
extern "C" void kernel_launch(void* const* d_in, const int* in_sizes, int n_in,
                              void* d_out, int out_size)
{
    const float* x      = (const float*)d_in[0];
    // d_in[1] = additive causal mask — exactly causal, handled analytically
    const float* W_attn = (const float*)d_in[2];
    const float* b_attn = (const float*)d_in[3];
    const float* W_proj = (const float*)d_in[4];
    const float* b_proj = (const float*)d_in[5];
    float* out = (float*)d_out;

    float *qkv_p, *attn_p;
    __nv_bfloat16 *xh, *xl, *wah, *wal, *wph, *wpl, *ah, *al;
    cudaGetSymbolAddress((void**)&qkv_p, g_qkv);
    cudaGetSymbolAddress((void**)&attn_p, g_attn);
    cudaGetSymbolAddress((void**)&xh, g_xh);   cudaGetSymbolAddress((void**)&xl, g_xl);
    cudaGetSymbolAddress((void**)&wah, g_wah); cudaGetSymbolAddress((void**)&wal, g_wal);
    cudaGetSymbolAddress((void**)&wph, g_wph); cudaGetSymbolAddress((void**)&wpl, g_wpl);
    cudaGetSymbolAddress((void**)&ah, g_ah);   cudaGetSymbolAddress((void**)&al, g_al);

    static bool attr_done = false;
    if (!attr_done) {
        cudaFuncSetAttribute(mma_gemm, cudaFuncAttributeMaxDynamicSharedMemorySize, GEMM_SMEM);
        cudaFuncSetAttribute(attn_kernel, cudaFuncAttributeMaxDynamicSharedMemorySize,
                             (int)(3 * DH * 68 * sizeof(float)));
        attr_done = true;
    }

    // pre-pass: splits + weight transposes
    int n4x = SLEN * DM / 4;
    split_kernel<<<(n4x + 255) / 256, 256>>>((const float4*)x, (uint2*)xh, (uint2*)xl, n4x);
    tsplit_kernel<<<dim3(3 * DM / 32, DM / 32), dim3(32, 8)>>>(W_attn, wah, wal, DM, 3 * DM);
    tsplit_kernel<<<dim3(DM / 32, DM / 32), dim3(32, 8)>>>(W_proj, wph, wpl, DM, DM);

    // 1) QKV projection (tensor cores via mma.sync): [4096,3072] = x @ W_attn
    mma_gemm<<<dim3(3 * DM / 128, SLEN / 128), 256, GEMM_SMEM>>>(
        xh, xl, wah, wal, b_attn, qkv_p, SLEN, 3 * DM, DM);

    // 2) fused causal attention (fp32)
    size_t smem = (size_t)3 * DH * 68 * sizeof(float);
    attn_kernel<<<dim3(SLEN / 64, NH), 256, smem>>>(qkv_p, attn_p);

    // split attention output for the projection GEMM
    split_kernel<<<(n4x + 255) / 256, 256>>>((const float4*)attn_p, (uint2*)ah, (uint2*)al, n4x);

    // 3) output projection (tensor cores via mma.sync): [4096,1024] = a @ W_proj
    mma_gemm<<<dim3(DM / 128, SLEN / 128), 256, GEMM_SMEM>>>(
        ah, al, wph, wpl, b_proj, out, SLEN, DM, DM);
}

// round 10
// speedup vs baseline: 3.2858x; 2.4438x over previous
#include <cuda_runtime.h>
#include <cuda_bf16.h>
#include <cstdint>

#define SLEN 4096
#define DM   1024
#define NH   16
#define DH   64
#define QKV_LD (3*DM)

// ---------------- device-global scratch (no allocs allowed) ----------------
__device__ __nv_bfloat16 g_xh[(size_t)SLEN * DM], g_xl[(size_t)SLEN * DM];     // x split [S,K]
__device__ __nv_bfloat16 g_wah[(size_t)3*DM*DM],  g_wal[(size_t)3*DM*DM];      // W_attn^T split [N,K]
__device__ __nv_bfloat16 g_wph[(size_t)DM*DM],    g_wpl[(size_t)DM*DM];        // W_proj^T split [N,K]
__device__ __nv_bfloat16 g_qh[(size_t)SLEN * QKV_LD], g_ql[(size_t)SLEN * QKV_LD]; // qkv split
__device__ __nv_bfloat16 g_ah[(size_t)SLEN * DM], g_al[(size_t)SLEN * DM];     // attn out split

// ---------------- helpers ----------------
__device__ __forceinline__ uint32_t smem_u32(const void* p) {
    uint32_t a;
    asm("{ .reg .u64 t; cvta.to.shared.u64 t, %1; cvt.u32.u64 %0, t; }" : "=r"(a) : "l"(p));
    return a;
}
__device__ __forceinline__ void cp16(uint32_t s, const void* g) {
    asm volatile("cp.async.cg.shared.global [%0], [%1], 16;" :: "r"(s), "l"(g));
}
__device__ __forceinline__ void ldsm4(uint32_t a, uint32_t r[4]) {
    asm volatile("ldmatrix.sync.aligned.m8n8.x4.shared.b16 {%0,%1,%2,%3}, [%4];"
                 : "=r"(r[0]), "=r"(r[1]), "=r"(r[2]), "=r"(r[3]) : "r"(a));
}
__device__ __forceinline__ void ldsm4t(uint32_t a, uint32_t r[4]) {
    asm volatile("ldmatrix.sync.aligned.m8n8.x4.trans.shared.b16 {%0,%1,%2,%3}, [%4];"
                 : "=r"(r[0]), "=r"(r[1]), "=r"(r[2]), "=r"(r[3]) : "r"(a));
}
__device__ __forceinline__ void mma16816(float c[4], const uint32_t a[4], uint32_t b0, uint32_t b1) {
    asm volatile("mma.sync.aligned.m16n8k16.row.col.f32.bf16.bf16.f32 "
                 "{%0,%1,%2,%3}, {%4,%5,%6,%7}, {%8,%9}, {%0,%1,%2,%3};"
                 : "+f"(c[0]), "+f"(c[1]), "+f"(c[2]), "+f"(c[3])
                 : "r"(a[0]), "r"(a[1]), "r"(a[2]), "r"(a[3]), "r"(b0), "r"(b1));
}
// pack (a->low, b->high) as bf16x2
__device__ __forceinline__ uint32_t pkf(float a, float b) {
    uint32_t r;
    asm("cvt.rn.bf16x2.f32 %0, %1, %2;" : "=r"(r) : "f"(b), "f"(a));
    return r;
}
__device__ __forceinline__ float lowf(uint32_t x)  { return __uint_as_float(x << 16); }
__device__ __forceinline__ float highf(uint32_t x) { return __uint_as_float(x & 0xFFFF0000u); }

// fast exp2 on the FMA pipe (t <= 0), rel err ~1.5e-5
__device__ __forceinline__ float fexp2(float t) {
    t = fmaxf(t, -126.f);
    float fi = floorf(t);
    float f = t - fi;
    float p = 1.53998e-4f;
    p = fmaf(p, f, 1.33336e-3f);
    p = fmaf(p, f, 9.61813e-3f);
    p = fmaf(p, f, 5.55041e-2f);
    p = fmaf(p, f, 2.40227e-1f);
    p = fmaf(p, f, 6.93147e-1f);
    p = fmaf(p, f, 1.0f);
    return p * __int_as_float(((int)fi + 127) << 23);
}

// ---------------- pre-pass: fp32 -> bf16 hi/lo split ----------------
__global__ void split_kernel(const float4* __restrict__ in, uint2* __restrict__ hi,
                             uint2* __restrict__ lo, int n4)
{
    int i = blockIdx.x * 256 + threadIdx.x;
    if (i >= n4) return;
    float4 v = in[i];
    uint32_t h01 = pkf(v.x, v.y), h23 = pkf(v.z, v.w);
    uint32_t l01 = pkf(v.x - lowf(h01), v.y - highf(h01));
    uint32_t l23 = pkf(v.z - lowf(h23), v.w - highf(h23));
    hi[i] = make_uint2(h01, h23);
    lo[i] = make_uint2(l01, l23);
}

// ---------------- pre-pass: transpose + split  W[K,N] -> T[N,K] hi/lo ----------------
__global__ void tsplit_kernel(const float* __restrict__ W, __nv_bfloat16* __restrict__ Th,
                              __nv_bfloat16* __restrict__ Tl, int K, int N)
{
    __shared__ float t[32][33];
    int bx = blockIdx.x, by = blockIdx.y;
    int x = bx * 32 + threadIdx.x;
#pragma unroll
    for (int i = 0; i < 32; i += 8)
        t[threadIdx.y + i][threadIdx.x] = W[(size_t)(by * 32 + threadIdx.y + i) * N + x];
    __syncthreads();
    int kx = by * 32 + threadIdx.x;
#pragma unroll
    for (int i = 0; i < 32; i += 8) {
        float v = t[threadIdx.x][threadIdx.y + i];
        __nv_bfloat16 h = __float2bfloat16(v);
        size_t o = (size_t)(bx * 32 + threadIdx.y + i) * K + kx;
        Th[o] = h;
        Tl[o] = __float2bfloat16(v - __bfloat162float(h));
    }
}

// ---------------------------------------------------------------------------
// mma.sync GEMM: C = (Ah+Al)[M,K] @ (Bh+Bl)[N,K]^T + bias
// Output either fp32 (Cf) or bf16 hi/lo split (Ch/Cl).
// ---------------------------------------------------------------------------
#define KC        64
#define TILE_B    16384
#define STG_B     (4 * TILE_B)
#define GEMM_SMEM (2 * STG_B)           // 131072 B

__global__ __launch_bounds__(256, 1)
void mma_gemm(const __nv_bfloat16* __restrict__ Ah, const __nv_bfloat16* __restrict__ Al,
              const __nv_bfloat16* __restrict__ Bh, const __nv_bfloat16* __restrict__ Bl,
              const float* __restrict__ bias, float* __restrict__ Cf,
              __nv_bfloat16* __restrict__ Ch, __nv_bfloat16* __restrict__ Cl,
              int M, int N, int K)
{
    extern __shared__ char smem[];
    uint32_t sb = smem_u32(smem);
    int tid = threadIdx.x;
    int l   = tid & 31;
    int wid = tid >> 5;
    int bn = blockIdx.x, bm = blockIdx.y;

    int rb  = tid >> 3;
    int c16 = tid & 7;
    uint32_t sw = (uint32_t)((c16 ^ (rb & 7)) << 4);

    const __nv_bfloat16* A0h = Ah + (size_t)(bm * 128 + rb) * K + c16 * 8;
    const __nv_bfloat16* A0l = Al + (size_t)(bm * 128 + rb) * K + c16 * 8;
    const __nv_bfloat16* B0h = Bh + (size_t)(bn * 128 + rb) * K + c16 * 8;
    const __nv_bfloat16* B0l = Bl + (size_t)(bn * 128 + rb) * K + c16 * 8;

    auto load_chunk = [&](int c, int st) {
        uint32_t s0 = sb + st * STG_B;
        size_t gofs = (size_t)c * KC;
#pragma unroll
        for (int p = 0; p < 4; p++) {
            uint32_t so = (uint32_t)(rb + 32 * p) * 128 + sw;
            size_t go = (size_t)(32 * p) * K + gofs;
            cp16(s0 + so,              A0h + go);
            cp16(s0 + TILE_B + so,     A0l + go);
            cp16(s0 + 2 * TILE_B + so, B0h + go);
            cp16(s0 + 3 * TILE_B + so, B0l + go);
        }
        asm volatile("cp.async.commit_group;" ::: "memory");
    };

    int wm = wid >> 1, wn = wid & 1;
    int m0 = wm * 32, n0 = wn * 64;

    int rowA_lane = l & 15;
    int k16A      = l >> 4;
    int r7a       = rowA_lane & 7;
    int rowB_lane = (l & 7) + 8 * (l >> 4);
    int k16B      = (l >> 3) & 1;
    int r7b       = l & 7;

    float acc[2][8][4];
#pragma unroll
    for (int mf = 0; mf < 2; mf++)
#pragma unroll
        for (int nf = 0; nf < 8; nf++)
#pragma unroll
            for (int q = 0; q < 4; q++) acc[mf][nf][q] = 0.f;

    auto compute = [&](int st) {
        uint32_t base = sb + st * STG_B;
#pragma unroll
        for (int ks = 0; ks < 4; ks++) {
            uint32_t ah[2][4], al[2][4];
#pragma unroll
            for (int mf = 0; mf < 2; mf++) {
                uint32_t row = (uint32_t)(m0 + mf * 16 + rowA_lane);
                uint32_t off = row * 128 + (uint32_t)(((ks * 2 + k16A) ^ r7a) << 4);
                ldsm4(base + off,          ah[mf]);
                ldsm4(base + TILE_B + off, al[mf]);
            }
#pragma unroll
            for (int nfp = 0; nfp < 4; nfp++) {
                uint32_t row = (uint32_t)(n0 + nfp * 16 + rowB_lane);
                uint32_t off = row * 128 + (uint32_t)(((ks * 2 + k16B) ^ r7b) << 4);
                uint32_t bh[4], bl[4];
                ldsm4(base + 2 * TILE_B + off, bh);
                ldsm4(base + 3 * TILE_B + off, bl);
#pragma unroll
                for (int mf = 0; mf < 2; mf++) {
#pragma unroll
                    for (int nf = 0; nf < 2; nf++) {
                        float* c = acc[mf][nfp * 2 + nf];
                        mma16816(c, ah[mf], bh[2 * nf], bh[2 * nf + 1]);
                        mma16816(c, ah[mf], bl[2 * nf], bl[2 * nf + 1]);
                        mma16816(c, al[mf], bh[2 * nf], bh[2 * nf + 1]);
                    }
                }
            }
        }
    };

    int NCH = K / KC;
    load_chunk(0, 0);
    for (int j = 0; j < NCH; j++) {
        if (j + 1 < NCH) {
            load_chunk(j + 1, (j + 1) & 1);
            asm volatile("cp.async.wait_group 1;" ::: "memory");
        } else {
            asm volatile("cp.async.wait_group 0;" ::: "memory");
        }
        __syncthreads();
        compute(j & 1);
        __syncthreads();
    }

#pragma unroll
    for (int mf = 0; mf < 2; mf++) {
        int r0 = bm * 128 + m0 + mf * 16 + (l >> 2);
#pragma unroll
        for (int nfp = 0; nfp < 4; nfp++) {
#pragma unroll
            for (int nf = 0; nf < 2; nf++) {
                int col = bn * 128 + n0 + nfp * 16 + nf * 8 + 2 * (l & 3);
                float2 bv = *(const float2*)&bias[col];
                const float* c = acc[mf][nfp * 2 + nf];
                float a0 = c[0] + bv.x, a1 = c[1] + bv.y;
                float a2 = c[2] + bv.x, a3 = c[3] + bv.y;
                if (Cf) {
                    *(float2*)&Cf[(size_t)r0 * N + col]       = make_float2(a0, a1);
                    *(float2*)&Cf[(size_t)(r0 + 8) * N + col] = make_float2(a2, a3);
                } else {
                    uint32_t h0 = pkf(a0, a1), h1 = pkf(a2, a3);
                    uint32_t l0 = pkf(a0 - lowf(h0), a1 - highf(h0));
                    uint32_t l1 = pkf(a2 - lowf(h1), a3 - highf(h1));
                    *(uint32_t*)&Ch[(size_t)r0 * N + col]       = h0;
                    *(uint32_t*)&Cl[(size_t)r0 * N + col]       = l0;
                    *(uint32_t*)&Ch[(size_t)(r0 + 8) * N + col] = h1;
                    *(uint32_t*)&Cl[(size_t)(r0 + 8) * N + col] = l1;
                }
            }
        }
    }
}

// ---------------------------------------------------------------------------
// mma.sync flash attention, split bf16, causal.
// CTA = 128 queries x 1 head, 8 warps x 16 q-rows, key blocks of 128.
// smem: Qh/Ql (32KB) + 2 stages x {Kh,Kl,Vh,Vl} (64KB each) = 160KB.
// ---------------------------------------------------------------------------
#define AT_SMEM (32768 + 2 * 65536)

__global__ __launch_bounds__(256, 1)
void attn_mma(const __nv_bfloat16* __restrict__ qkh, const __nv_bfloat16* __restrict__ qkl,
              __nv_bfloat16* __restrict__ oh, __nv_bfloat16* __restrict__ ol)
{
    extern __shared__ char smem[];
    uint32_t sb = smem_u32(smem);
    const int tid = threadIdx.x;
    const int l = tid & 31;
    const int w = tid >> 5;
    // heavy (large qb) CTAs first in launch order
    int flat = (int)blockIdx.y * 32 + (int)blockIdx.x;
    const int h  = flat & 15;
    const int qb = 31 - (flat >> 4);
    const size_t hofs = (size_t)h * DH;

    // ---- Q tile load (cp.async group 0) ----
    {
        int rb = tid >> 2, c2 = tid & 3;
#pragma unroll
        for (int rh = 0; rh < 2; rh++)
#pragma unroll
            for (int cc = 0; cc < 2; cc++) {
                int row = rb + rh * 64, c16 = c2 + cc * 4;
                uint32_t so = (uint32_t)row * 128 + (uint32_t)((c16 ^ (row & 7)) << 4);
                size_t go = (size_t)(qb * 128 + row) * QKV_LD + hofs + c16 * 8;
                cp16(sb + so,         qkh + go);
                cp16(sb + 16384 + so, qkl + go);
            }
        asm volatile("cp.async.commit_group;" ::: "memory");
    }
    auto load_kv = [&](int kb, int st) {
        uint32_t s0 = sb + 32768 + st * 65536;
        int rb = tid >> 2, c2 = tid & 3;
#pragma unroll
        for (int rh = 0; rh < 2; rh++)
#pragma unroll
            for (int cc = 0; cc < 2; cc++) {
                int row = rb + rh * 64, c16 = c2 + cc * 4;
                uint32_t so = (uint32_t)row * 128 + (uint32_t)((c16 ^ (row & 7)) << 4);
                size_t gk = (size_t)(kb * 128 + row) * QKV_LD + DM + hofs + c16 * 8;
                size_t gv = gk + DM;
                cp16(s0 + so,         qkh + gk);
                cp16(s0 + 16384 + so, qkl + gk);
                cp16(s0 + 32768 + so, qkh + gv);
                cp16(s0 + 49152 + so, qkl + gv);
            }
        asm volatile("cp.async.commit_group;" ::: "memory");
    };
    load_kv(0, 0);

    const int g    = l >> 2;
    const int rowA = l & 15, kA = l >> 4;
    const int rowB = (l & 7) + 8 * (l >> 4), kB = (l >> 3) & 1;
    const int rowV = (l & 7) + 8 * ((l >> 3) & 1), cV = l >> 4;
    const float CE = 0.125f * 1.44269504f;   // scale * log2(e)

    uint32_t qfh[4][4], qfl[4][4];
    float O[8][4];
    float mrow0 = -1e30f, mrow1 = -1e30f, ls0 = 0.f, ls1 = 0.f;
#pragma unroll
    for (int i = 0; i < 8; i++)
#pragma unroll
        for (int q = 0; q < 4; q++) O[i][q] = 0.f;

    for (int j = 0; j <= qb; j++) {
        if (j < qb) {
            load_kv(j + 1, (j + 1) & 1);
            asm volatile("cp.async.wait_group 1;" ::: "memory");
        } else {
            asm volatile("cp.async.wait_group 0;" ::: "memory");
        }
        __syncthreads();
        if (j == 0) {   // Q frags -> registers, once
#pragma unroll
            for (int t = 0; t < 4; t++) {
                int row = w * 16 + rowA;
                uint32_t off = (uint32_t)row * 128 + (uint32_t)((((t * 2 + kA) ^ (row & 7))) << 4);
                ldsm4(sb + off,         qfh[t]);
                ldsm4(sb + 16384 + off, qfl[t]);
            }
        }
        uint32_t base = sb + 32768 + (uint32_t)(j & 1) * 65536;

        // ---- S = Q K^T (split, 3 terms) ----
        float S[16][4];
#pragma unroll
        for (int a = 0; a < 16; a++)
#pragma unroll
            for (int b = 0; b < 4; b++) S[a][b] = 0.f;

#pragma unroll
        for (int np = 0; np < 8; np++) {
#pragma unroll
            for (int t = 0; t < 4; t++) {
                int row = np * 16 + rowB;
                uint32_t off = (uint32_t)row * 128 + (uint32_t)((((t * 2 + kB) ^ (row & 7))) << 4);
                uint32_t kh[4], kl[4];
                ldsm4(base + off,         kh);
                ldsm4(base + 16384 + off, kl);
                mma16816(S[2 * np],     qfh[t], kh[0], kh[1]);
                mma16816(S[2 * np],     qfh[t], kl[0], kl[1]);
                mma16816(S[2 * np],     qfl[t], kh[0], kh[1]);
                mma16816(S[2 * np + 1], qfh[t], kh[2], kh[3]);
                mma16816(S[2 * np + 1], qfh[t], kl[2], kl[3]);
                mma16816(S[2 * np + 1], qfl[t], kh[2], kh[3]);
            }
        }

        if (j == qb) {   // causal mask inside diagonal 128-block
            int r0 = w * 16 + g;
#pragma unroll
            for (int nf = 0; nf < 16; nf++) {
                int c0 = nf * 8 + 2 * (l & 3);
                if (c0     > r0)     S[nf][0] = -1e30f;
                if (c0 + 1 > r0)     S[nf][1] = -1e30f;
                if (c0     > r0 + 8) S[nf][2] = -1e30f;
                if (c0 + 1 > r0 + 8) S[nf][3] = -1e30f;
            }
        }

        // ---- online softmax ----
        float mx0 = -1e30f, mx1 = -1e30f;
#pragma unroll
        for (int nf = 0; nf < 16; nf++) {
            mx0 = fmaxf(mx0, fmaxf(S[nf][0], S[nf][1]));
            mx1 = fmaxf(mx1, fmaxf(S[nf][2], S[nf][3]));
        }
        mx0 = fmaxf(mx0, __shfl_xor_sync(0xffffffffu, mx0, 1));
        mx0 = fmaxf(mx0, __shfl_xor_sync(0xffffffffu, mx0, 2));
        mx1 = fmaxf(mx1, __shfl_xor_sync(0xffffffffu, mx1, 1));
        mx1 = fmaxf(mx1, __shfl_xor_sync(0xffffffffu, mx1, 2));
        float mn0 = fmaxf(mrow0, mx0), mn1 = fmaxf(mrow1, mx1);
        float cr0 = fexp2((mrow0 - mn0) * CE), cr1 = fexp2((mrow1 - mn1) * CE);
        mrow0 = mn0; mrow1 = mn1;
        float nm0 = mn0 * CE, nm1 = mn1 * CE;
#pragma unroll
        for (int nf = 0; nf < 8; nf++) {
            O[nf][0] *= cr0; O[nf][1] *= cr0;
            O[nf][2] *= cr1; O[nf][3] *= cr1;
        }
        float s0 = 0.f, s1 = 0.f;
        // exp + split; pack P frags in place (S[2t]=hi A-frag, S[2t+1]=lo A-frag)
#pragma unroll
        for (int t = 0; t < 8; t++) {
            float p00 = fexp2(fmaf(S[2*t][0],   CE, -nm0));
            float p01 = fexp2(fmaf(S[2*t][1],   CE, -nm0));
            float p02 = fexp2(fmaf(S[2*t][2],   CE, -nm1));
            float p03 = fexp2(fmaf(S[2*t][3],   CE, -nm1));
            float p10 = fexp2(fmaf(S[2*t+1][0], CE, -nm0));
            float p11 = fexp2(fmaf(S[2*t+1][1], CE, -nm0));
            float p12 = fexp2(fmaf(S[2*t+1][2], CE, -nm1));
            float p13 = fexp2(fmaf(S[2*t+1][3], CE, -nm1));
            s0 += (p00 + p01) + (p10 + p11);
            s1 += (p02 + p03) + (p12 + p13);
            uint32_t h0 = pkf(p00, p01), h1 = pkf(p02, p03);
            uint32_t h2 = pkf(p10, p11), h3 = pkf(p12, p13);
            uint32_t e0 = pkf(p00 - lowf(h0), p01 - highf(h0));
            uint32_t e1 = pkf(p02 - lowf(h1), p03 - highf(h1));
            uint32_t e2 = pkf(p10 - lowf(h2), p11 - highf(h2));
            uint32_t e3 = pkf(p12 - lowf(h3), p13 - highf(h3));
            S[2*t][0]   = __uint_as_float(h0);
            S[2*t][1]   = __uint_as_float(h1);
            S[2*t][2]   = __uint_as_float(h2);
            S[2*t][3]   = __uint_as_float(h3);
            S[2*t+1][0] = __uint_as_float(e0);
            S[2*t+1][1] = __uint_as_float(e1);
            S[2*t+1][2] = __uint_as_float(e2);
            S[2*t+1][3] = __uint_as_float(e3);
        }
        ls0 = ls0 * cr0 + s0;
        ls1 = ls1 * cr1 + s1;

        // ---- O += P V (split, 3 terms), V frags via ldmatrix.trans ----
#pragma unroll
        for (int t = 0; t < 8; t++) {
            uint32_t Ahf[4] = {__float_as_uint(S[2*t][0]),   __float_as_uint(S[2*t][1]),
                               __float_as_uint(S[2*t][2]),   __float_as_uint(S[2*t][3])};
            uint32_t Alf[4] = {__float_as_uint(S[2*t+1][0]), __float_as_uint(S[2*t+1][1]),
                               __float_as_uint(S[2*t+1][2]), __float_as_uint(S[2*t+1][3])};
#pragma unroll
            for (int vp = 0; vp < 4; vp++) {
                int row = t * 16 + rowV;
                uint32_t off = (uint32_t)row * 128 + (uint32_t)((((vp * 2 + cV) ^ (row & 7))) << 4);
                uint32_t vh[4], vl[4];
                ldsm4t(base + 32768 + off, vh);
                ldsm4t(base + 49152 + off, vl);
                mma16816(O[2 * vp],     Ahf, vh[0], vh[1]);
                mma16816(O[2 * vp],     Ahf, vl[0], vl[1]);
                mma16816(O[2 * vp],     Alf, vh[0], vh[1]);
                mma16816(O[2 * vp + 1], Ahf, vh[2], vh[3]);
                mma16816(O[2 * vp + 1], Ahf, vl[2], vl[3]);
                mma16816(O[2 * vp + 1], Alf, vh[2], vh[3]);
            }
        }
        __syncthreads();
    }

    // ---- finalize: reduce l across the 4 lanes per row, write split output ----
    ls0 += __shfl_xor_sync(0xffffffffu, ls0, 1);
    ls0 += __shfl_xor_sync(0xffffffffu, ls0, 2);
    ls1 += __shfl_xor_sync(0xffffffffu, ls1, 1);
    ls1 += __shfl_xor_sync(0xffffffffu, ls1, 2);
    float inv0 = 1.f / ls0, inv1 = 1.f / ls1;
    int r0 = qb * 128 + w * 16 + g;
#pragma unroll
    for (int nf = 0; nf < 8; nf++) {
        int col = nf * 8 + 2 * (l & 3);
        size_t o0 = (size_t)r0 * DM + hofs + col;
        size_t o1 = (size_t)(r0 + 8) * DM + hofs + col;
        float a0 = O[nf][0] * inv0, a1 = O[nf][1] * inv0;
        float a2 = O[nf][2] * inv1, a3 = O[nf][3] * inv1;
        uint32_t h0 = pkf(a0, a1), h1 = pkf(a2, a3);
        *(uint32_t*)&oh[o0] = h0;
        *(uint32_t*)&ol[o0] = pkf(a0 - lowf(h0), a1 - highf(h0));
        *(uint32_t*)&oh[o1] = h1;
        *(uint32_t*)&ol[o1] = pkf(a2 - lowf(h1), a3 - highf(h1));
    }
}

// ---------------------------------------------------------------------------
extern "C" void kernel_launch(void* const* d_in, const int* in_sizes, int n_in,
                              void* d_out, int out_size)
{
    const float* x      = (const float*)d_in[0];
    // d_in[1] = additive causal mask — exactly causal, handled analytically
    const float* W_attn = (const float*)d_in[2];
    const float* b_attn = (const float*)d_in[3];
    const float* W_proj = (const float*)d_in[4];
    const float* b_proj = (const float*)d_in[5];
    float* out = (float*)d_out;

    __nv_bfloat16 *xh, *xl, *wah, *wal, *wph, *wpl, *qh, *ql, *ah, *al;
    cudaGetSymbolAddress((void**)&xh, g_xh);   cudaGetSymbolAddress((void**)&xl, g_xl);
    cudaGetSymbolAddress((void**)&wah, g_wah); cudaGetSymbolAddress((void**)&wal, g_wal);
    cudaGetSymbolAddress((void**)&wph, g_wph); cudaGetSymbolAddress((void**)&wpl, g_wpl);
    cudaGetSymbolAddress((void**)&qh, g_qh);   cudaGetSymbolAddress((void**)&ql, g_ql);
    cudaGetSymbolAddress((void**)&ah, g_ah);   cudaGetSymbolAddress((void**)&al, g_al);

    static bool attr_done = false;
    if (!attr_done) {
        cudaFuncSetAttribute(mma_gemm, cudaFuncAttributeMaxDynamicSharedMemorySize, GEMM_SMEM);
        cudaFuncSetAttribute(attn_mma, cudaFuncAttributeMaxDynamicSharedMemorySize, AT_SMEM);
        attr_done = true;
    }

    // pre-pass
    int n4x = SLEN * DM / 4;
    split_kernel<<<(n4x + 255) / 256, 256>>>((const float4*)x, (uint2*)xh, (uint2*)xl, n4x);
    tsplit_kernel<<<dim3(3 * DM / 32, DM / 32), dim3(32, 8)>>>(W_attn, wah, wal, DM, 3 * DM);
    tsplit_kernel<<<dim3(DM / 32, DM / 32), dim3(32, 8)>>>(W_proj, wph, wpl, DM, DM);

    // 1) QKV projection -> bf16 split qkv
    mma_gemm<<<dim3(3 * DM / 128, SLEN / 128), 256, GEMM_SMEM>>>(
        xh, xl, wah, wal, b_attn, nullptr, qh, ql, SLEN, 3 * DM, DM);

    // 2) tensor-core flash attention -> bf16 split output
    attn_mma<<<dim3(32, 16), 256, AT_SMEM>>>(qh, ql, ah, al);

    // 3) output projection -> fp32
    mma_gemm<<<dim3(DM / 128, SLEN / 128), 256, GEMM_SMEM>>>(
        ah, al, wph, wpl, b_proj, out, nullptr, nullptr, SLEN, DM, DM);
}